// round 6
// baseline (speedup 1.0000x reference)
#include <cuda_runtime.h>
#include <math.h>
#include <stdint.h>

#define SEQ 50
#define DIM 32
#define NTHR 256
#define NWARP 8
#define FULLM 0xffffffffu
#define WP 34                 // weight row pitch (floats): even -> 8B-aligned u64 loads

typedef unsigned long long u64;

// packed fp32x2 helpers (Blackwell FFMA2 path, PTX-only)
__device__ __forceinline__ u64 fma2(u64 a, u64 b, u64 c) {
    u64 d;
    asm("fma.rn.f32x2 %0, %1, %2, %3;" : "=l"(d) : "l"(a), "l"(b), "l"(c));
    return d;
}
__device__ __forceinline__ u64 add2(u64 a, u64 b) {
    u64 d;
    asm("add.rn.f32x2 %0, %1, %2;" : "=l"(d) : "l"(a), "l"(b));
    return d;
}
__device__ __forceinline__ u64 mul2(u64 a, u64 b) {
    u64 d;
    asm("mul.rn.f32x2 %0, %1, %2;" : "=l"(d) : "l"(a), "l"(b));
    return d;
}
__device__ __forceinline__ u64 pack2(float lo, float hi) {
    u64 d;
    asm("mov.b64 %0, {%1, %2};" : "=l"(d) : "r"(__float_as_uint(lo)), "r"(__float_as_uint(hi)));
    return d;
}
__device__ __forceinline__ float hsum2(u64 a) {
    unsigned lo, hi;
    asm("mov.b64 {%0, %1}, %2;" : "=r"(lo), "=r"(hi) : "l"(a));
    return __uint_as_float(lo) + __uint_as_float(hi);
}

// Folded weights, shared by all batches (computed once by prep_kernel)
__device__ float gWfold[3 * DIM * DIM];   // rows pre-scaled by ln_g
__device__ float gB2[3 * DIM];            // bias + b . W^T
__device__ float gSw[3 * DIM];            // rowsum of g-scaled W

__global__ void prep_kernel(
    const float* __restrict__ ln_g, const float* __restrict__ ln_b,
    const float* __restrict__ Wq, const float* __restrict__ bq,
    const float* __restrict__ Wk, const float* __restrict__ bk,
    const float* __restrict__ Wv, const float* __restrict__ bv)
{
    int j = threadIdx.x;
    if (j >= 3 * DIM) return;
    int t = j >> 5, r = j & 31;
    const float* W    = (t == 0) ? Wq : (t == 1) ? Wk : Wv;
    const float* bias = (t == 0) ? bq : (t == 1) ? bk : bv;
    float b2 = bias[r], sw = 0.f;
    #pragma unroll
    for (int d = 0; d < DIM; d++) {
        float w  = W[r * DIM + d];
        float gw = w * ln_g[d];
        b2 = fmaf(w, ln_b[d], b2);
        sw += gw;
        gWfold[(t * DIM + r) * DIM + d] = gw;
    }
    gB2[j] = b2;
    gSw[j] = sw;
}

__global__ __launch_bounds__(NTHR, 4) void mha_fused_kernel(
    const float* __restrict__ Q, const float* __restrict__ K, const float* __restrict__ V,
    const float* __restrict__ Wo, const float* __restrict__ bo,
    float* __restrict__ out)
{
    __shared__ __align__(16) float sbuf[3 * SEQ * DIM];  // projected q,k,v; q region becomes ctx
    __shared__ __align__(16) float sW[4 * DIM * WP];     // folded Wq,Wk,Wv + raw Wo
    __shared__ float2 sStats[3 * SEQ];                   // (mu, inv) per row
    __shared__ float sB2[3 * DIM], sSw[3 * DIM], sboS[DIM];

    const int tid  = threadIdx.x;
    const int lane = tid & 31;
    const int wid  = tid >> 5;
    const size_t boff = (size_t)blockIdx.x * (SEQ * DIM);
    const float* Qb = Q + boff;
    const float* Kb = K + boff;
    const float* Vb = V + boff;

    // ---- stage weights into padded smem ----
    for (int i = tid; i < 4 * DIM * DIM; i += NTHR) {
        int t = i >> 10, idx = i & 1023, r = idx >> 5, c = idx & 31;
        sW[t * DIM * WP + r * WP + c] = (t < 3) ? gWfold[i] : Wo[idx];
    }
    if (tid < 3 * DIM) { sB2[tid] = gB2[tid]; sSw[tid] = gSw[tid]; }
    else if (tid < 4 * DIM) sboS[tid - 3 * DIM] = bo[tid - 3 * DIM];

    // ---- LN stats only (x NOT staged; re-read from L1 later) ----
    {
        const int rsub = lane >> 3;   // 0..3: row within 4-row block
        const int rk   = lane & 7;    // float4 segment within row
        for (int blk = wid; blk < (3 * SEQ + 3) / 4; blk += NWARP) {
            int gr = blk * 4 + rsub;
            float4 xv = make_float4(0.f, 0.f, 0.f, 0.f);
            if (gr < 3 * SEQ) {
                int t = gr / SEQ;
                int r = gr - t * SEQ;
                const float* src = (t == 0) ? Qb : (t == 1) ? Kb : Vb;
                xv = *(const float4*)(src + r * DIM + rk * 4);
            }
            float s1 = xv.x + xv.y + xv.z + xv.w;
            float s2 = xv.x * xv.x + xv.y * xv.y + xv.z * xv.z + xv.w * xv.w;
            #pragma unroll
            for (int o = 4; o; o >>= 1) {
                s1 += __shfl_xor_sync(FULLM, s1, o);
                s2 += __shfl_xor_sync(FULLM, s2, o);
            }
            if (rk == 0 && gr < 3 * SEQ) {
                float mu  = s1 * (1.0f / DIM);
                float var = s2 * (1.0f / DIM) - mu * mu;
                sStats[gr] = make_float2(mu, rsqrtf(var + 1e-5f));
            }
        }
    }
    __syncthreads();

    // ---- projections: lane = output col; packed FFMA2 dot; x via broadcast LDG ----
    {
        u64 wreg[16];
        float b2 = 0.f, swv = 0.f;
        int tprev = -1;
        #pragma unroll
        for (int k = 0; k < 3; k++) {
            const int task = wid * 3 + k;       // 24 tasks: 3 tensors x 8 chunks
            const int t = task >> 3;
            const int c = task & 7;
            if (t != tprev) {
                const float* wr = sW + (t * DIM + lane) * WP;
                #pragma unroll
                for (int d = 0; d < 16; d++) wreg[d] = *(const u64*)(wr + d * 2);
                b2  = sB2[t * DIM + lane];
                swv = sSw[t * DIM + lane];
                tprev = t;
            }
            const int r0 = (c * SEQ) >> 3;
            const int r1 = ((c + 1) * SEQ) >> 3;
            const float* src = (t == 0) ? Qb : (t == 1) ? Kb : Vb;
            for (int r = r0; r < r1; r++) {
                const ulonglong2* xr = (const ulonglong2*)(src + r * DIM);
                u64 acc0 = 0ull, acc1 = 0ull;
                #pragma unroll
                for (int i = 0; i < 8; i++) {
                    ulonglong2 xv = xr[i];
                    acc0 = fma2(xv.x, wreg[2 * i],     acc0);
                    acc1 = fma2(xv.y, wreg[2 * i + 1], acc1);
                }
                float dot = hsum2(add2(acc0, acc1));
                float2 st = sStats[t * SEQ + r];
                sbuf[(t * SEQ + r) * DIM + lane] =
                    fmaf(st.y, fmaf(-st.x, swv, dot), b2);
            }
        }
    }
    __syncthreads();

    // ---- paired causal attention (packed): thread = (head, pair p) ----
    if (tid < 4 * (SEQ / 2)) {
        const int h = tid & 3;
        const int p = tid >> 2;           // 0..24
        const int i2 = SEQ - 1 - p;       // 25..49
        const float* sk_ = sbuf + SEQ * DIM;
        const float* sv_ = sbuf + 2 * SEQ * DIM;
        const u64 scale2 = pack2(0.35355339059327373f, 0.35355339059327373f);

        const ulonglong2* q1p = (const ulonglong2*)(sbuf + p  * DIM + h * 8);
        const ulonglong2* q2p = (const ulonglong2*)(sbuf + i2 * DIM + h * 8);
        ulonglong2 q1l = q1p[0], q1h = q1p[1];
        ulonglong2 q2l = q2p[0], q2h = q2p[1];
        u64 q1[4] = { mul2(q1l.x, scale2), mul2(q1l.y, scale2),
                      mul2(q1h.x, scale2), mul2(q1h.y, scale2) };
        u64 q2[4] = { mul2(q2l.x, scale2), mul2(q2l.y, scale2),
                      mul2(q2h.x, scale2), mul2(q2h.y, scale2) };

        float ssum1 = 0.f, ssum2 = 0.f;
        u64 a1[4] = {0ull, 0ull, 0ull, 0ull};
        u64 a2[4] = {0ull, 0ull, 0ull, 0ull};

        for (int j = 0; j <= i2; j++) {
            const ulonglong2* kr = (const ulonglong2*)(sk_ + j * DIM + h * 8);
            ulonglong2 kl = kr[0], kh = kr[1];
            const ulonglong2* vr = (const ulonglong2*)(sv_ + j * DIM + h * 8);
            ulonglong2 vl = vr[0], vh = vr[1];

            u64 s = fma2(q2[0], kl.x, (u64)0ull);
            s = fma2(q2[1], kl.y, s);
            s = fma2(q2[2], kh.x, s);
            s = fma2(q2[3], kh.y, s);
            float w2 = __expf(hsum2(s));
            ssum2 += w2;
            u64 w2p = pack2(w2, w2);
            a2[0] = fma2(w2p, vl.x, a2[0]);
            a2[1] = fma2(w2p, vl.y, a2[1]);
            a2[2] = fma2(w2p, vh.x, a2[2]);
            a2[3] = fma2(w2p, vh.y, a2[3]);

            if (j <= p) {
                u64 s1 = fma2(q1[0], kl.x, (u64)0ull);
                s1 = fma2(q1[1], kl.y, s1);
                s1 = fma2(q1[2], kh.x, s1);
                s1 = fma2(q1[3], kh.y, s1);
                float w1 = __expf(hsum2(s1));
                ssum1 += w1;
                u64 w1p = pack2(w1, w1);
                a1[0] = fma2(w1p, vl.x, a1[0]);
                a1[1] = fma2(w1p, vl.y, a1[1]);
                a1[2] = fma2(w1p, vh.x, a1[2]);
                a1[3] = fma2(w1p, vh.y, a1[3]);
            }
        }
        float i1v = 1.0f / ssum1;
        float i2v = 1.0f / ssum2;
        u64 i1p = pack2(i1v, i1v);
        u64 i2p = pack2(i2v, i2v);
        u64* c1 = (u64*)(sbuf + p  * DIM + h * 8);
        u64* c2 = (u64*)(sbuf + i2 * DIM + h * 8);
        #pragma unroll
        for (int d = 0; d < 4; d++) {
            c1[d] = mul2(a1[d], i1p);
            c2[d] = mul2(a2[d], i2p);
        }
    }
    __syncthreads();

    // ---- output projection + residual (Wo in regs, packed FFMA2) ----
    {
        u64 wreg[16];
        const float* wr = sW + (3 * DIM + lane) * WP;
        #pragma unroll
        for (int d = 0; d < 16; d++) wreg[d] = *(const u64*)(wr + d * 2);
        const float b2 = sboS[lane];
        float* ob = out + boff;
        const int r0 = (wid * SEQ) >> 3;
        const int r1 = ((wid + 1) * SEQ) >> 3;
        for (int r = r0; r < r1; r++) {
            const ulonglong2* xr = (const ulonglong2*)(sbuf + r * DIM);
            u64 acc0 = 0ull, acc1 = 0ull;
            #pragma unroll
            for (int i = 0; i < 8; i++) {
                ulonglong2 xv = xr[i];
                acc0 = fma2(xv.x, wreg[2 * i],     acc0);
                acc1 = fma2(xv.y, wreg[2 * i + 1], acc1);
            }
            float dot = hsum2(add2(acc0, acc1)) + b2;
            ob[r * DIM + lane] = dot + Qb[r * DIM + lane];
        }
    }
}

extern "C" void kernel_launch(void* const* d_in, const int* in_sizes, int n_in,
                              void* d_out, int out_size) {
    const float* Q    = (const float*)d_in[0];
    const float* K    = (const float*)d_in[1];
    const float* V    = (const float*)d_in[2];
    // d_in[3] = mask (static causal triu, implemented analytically)
    const float* ln_g = (const float*)d_in[4];
    const float* ln_b = (const float*)d_in[5];
    const float* Wq   = (const float*)d_in[6];
    const float* bq   = (const float*)d_in[7];
    const float* Wk   = (const float*)d_in[8];
    const float* bk   = (const float*)d_in[9];
    const float* Wv   = (const float*)d_in[10];
    const float* bv   = (const float*)d_in[11];
    const float* Wo   = (const float*)d_in[12];
    const float* bo   = (const float*)d_in[13];
    float* out = (float*)d_out;

    const int B = in_sizes[0] / (SEQ * DIM);  // 16384
    prep_kernel<<<1, 96>>>(ln_g, ln_b, Wq, bq, Wk, bk, Wv, bv);
    mha_fused_kernel<<<B, NTHR>>>(Q, K, V, Wo, bo, out);
}

// round 7
// speedup vs baseline: 1.3548x; 1.3548x over previous
#include <cuda_runtime.h>
#include <math.h>

#define SEQ 50
#define DIM 32
#define NTHR 256
#define NWARP 8
#define FULLM 0xffffffffu
#define WP 34

// Folded weights, shared by all batches (computed once by prep_kernel)
__device__ float gWfold[3 * DIM * DIM];   // rows pre-scaled by ln_g
__device__ float gB2[3 * DIM];            // bias + b . W^T
__device__ float gSw[3 * DIM];            // rowsum of g-scaled W

__global__ void prep_kernel(
    const float* __restrict__ ln_g, const float* __restrict__ ln_b,
    const float* __restrict__ Wq, const float* __restrict__ bq,
    const float* __restrict__ Wk, const float* __restrict__ bk,
    const float* __restrict__ Wv, const float* __restrict__ bv)
{
    int j = threadIdx.x;
    if (j >= 3 * DIM) return;
    int t = j >> 5, r = j & 31;
    const float* W    = (t == 0) ? Wq : (t == 1) ? Wk : Wv;
    const float* bias = (t == 0) ? bq : (t == 1) ? bk : bv;
    float b2 = bias[r], sw = 0.f;
    #pragma unroll
    for (int d = 0; d < DIM; d++) {
        float w  = W[r * DIM + d];
        float gw = w * ln_g[d];
        b2 = fmaf(w, ln_b[d], b2);
        sw += gw;
        gWfold[(t * DIM + r) * DIM + d] = gw;
    }
    gB2[j] = b2;
    gSw[j] = sw;
}

__global__ __launch_bounds__(NTHR, 4) void mha_fused_kernel(
    const float* __restrict__ Q, const float* __restrict__ K, const float* __restrict__ V,
    const float* __restrict__ Wo, const float* __restrict__ bo,
    float* __restrict__ out)
{
    __shared__ __align__(16) float sbuf[3 * SEQ * DIM];  // raw rows -> projected in place; q -> ctx
    __shared__ __align__(16) float sW[4 * DIM * WP];     // folded Wq,Wk,Wv + raw Wo
    __shared__ float2 sStats[3 * SEQ];                   // (mu, inv) per row
    __shared__ float sB2[3 * DIM], sSw[3 * DIM], sboS[DIM];

    const int tid  = threadIdx.x;
    const int lane = tid & 31;
    const int wid  = tid >> 5;
    const int cc   = lane & 15;      // column pair id
    const int kh   = lane >> 4;      // k-half: 0 -> k[0..16), 1 -> k[16..32)
    const size_t boff = (size_t)blockIdx.x * (SEQ * DIM);
    const float* Qb = Q + boff;
    const float* Kb = K + boff;
    const float* Vb = V + boff;

    // ---- stage weights (folded qkv from global, Wo raw) into padded smem ----
    for (int i = tid; i < 4 * DIM * DIM; i += NTHR) {
        int t = i >> 10, idx = i & 1023, r = idx >> 5, c = idx & 31;
        sW[t * DIM * WP + r * WP + c] = (t < 3) ? gWfold[i] : Wo[idx];
    }
    if (tid < 3 * DIM) { sB2[tid] = gB2[tid]; sSw[tid] = gSw[tid]; }
    else if (tid < 4 * DIM) sboS[tid - 3 * DIM] = bo[tid - 3 * DIM];

    // ---- raw row loads + LN stats (sum x, sum x^2), 4 rows per warp-iter ----
    {
        const int rsub = lane >> 3;
        const int rk   = lane & 7;
        for (int blk = wid; blk < (3 * SEQ + 3) / 4; blk += NWARP) {
            int gr = blk * 4 + rsub;
            float4 xv = make_float4(0.f, 0.f, 0.f, 0.f);
            if (gr < 3 * SEQ) {
                int t = gr / SEQ;
                int r = gr - t * SEQ;
                const float* src = (t == 0) ? Qb : (t == 1) ? Kb : Vb;
                xv = *(const float4*)(src + r * DIM + rk * 4);
                *(float4*)(sbuf + gr * DIM + rk * 4) = xv;
            }
            float s1 = xv.x + xv.y + xv.z + xv.w;
            float s2 = xv.x * xv.x + xv.y * xv.y + xv.z * xv.z + xv.w * xv.w;
            #pragma unroll
            for (int o = 4; o; o >>= 1) {
                s1 += __shfl_xor_sync(FULLM, s1, o);
                s2 += __shfl_xor_sync(FULLM, s2, o);
            }
            if (rk == 0 && gr < 3 * SEQ) {
                float mu  = s1 * (1.0f / DIM);
                float var = s2 * (1.0f / DIM) - mu * mu;
                sStats[gr] = make_float2(mu, rsqrtf(var + 1e-5f));
            }
        }
    }
    __syncthreads();

    // ---- projections, k-split: half-warps each cover 16 of the 32 k values;
    // lane holds weights for cols {cc, cc+16} over its k-half (32 regs total).
    // After shfl_xor(16) combine, lane keeps the dot for its natural col = lane.
    {
        float wreg0[16], wreg1[16];
        float b2 = 0.f, swv = 0.f;
        int tprev = -1;
        #pragma unroll
        for (int k = 0; k < 3; k++) {
            const int task = wid * 3 + k;       // 24 tasks: 3 tensors x 8 chunks
            const int t = task >> 3;
            const int c = task & 7;
            if (t != tprev) {
                const float* w0 = sW + (t * DIM + cc) * WP + kh * 16;
                const float* w1 = sW + (t * DIM + cc + 16) * WP + kh * 16;
                #pragma unroll
                for (int d = 0; d < 16; d++) { wreg0[d] = w0[d]; wreg1[d] = w1[d]; }
                b2  = sB2[t * DIM + lane];
                swv = sSw[t * DIM + lane];
                tprev = t;
            }
            const int r0 = (c * SEQ) >> 3;
            const int r1 = ((c + 1) * SEQ) >> 3;
            float* base = sbuf + t * SEQ * DIM;
            float orow[7];
            const int nr = r1 - r0;
            #pragma unroll
            for (int r = 0; r < 7; r++) {
                if (r < nr) {
                    const float4* xr = (const float4*)(base + (r0 + r) * DIM + kh * 16);
                    float p0a = 0.f, p0b = 0.f, p1a = 0.f, p1b = 0.f;
                    #pragma unroll
                    for (int i = 0; i < 4; i++) {
                        float4 xv = xr[i];
                        p0a = fmaf(xv.x, wreg0[4*i+0], fmaf(xv.y, wreg0[4*i+1], p0a));
                        p0b = fmaf(xv.z, wreg0[4*i+2], fmaf(xv.w, wreg0[4*i+3], p0b));
                        p1a = fmaf(xv.x, wreg1[4*i+0], fmaf(xv.y, wreg1[4*i+1], p1a));
                        p1b = fmaf(xv.z, wreg1[4*i+2], fmaf(xv.w, wreg1[4*i+3], p1b));
                    }
                    float part0 = p0a + p0b;
                    float part1 = p1a + p1b;
                    part0 += __shfl_xor_sync(FULLM, part0, 16);
                    part1 += __shfl_xor_sync(FULLM, part1, 16);
                    float dot = kh ? part1 : part0;       // col == lane
                    float2 st = sStats[t * SEQ + r0 + r];
                    orow[r] = fmaf(st.y, fmaf(-st.x, swv, dot), b2);
                }
            }
            __syncwarp();
            #pragma unroll
            for (int r = 0; r < 7; r++)
                if (r < nr) base[(r0 + r) * DIM + lane] = orow[r];
        }
    }
    __syncthreads();

    // ---- paired causal attention: thread = (head, pair p), queries p and 49-p ----
    if (tid < 4 * (SEQ / 2)) {
        const int h = tid & 3;
        const int p = tid >> 2;           // 0..24
        const int i2 = SEQ - 1 - p;       // 25..49
        const float* sk_ = sbuf + SEQ * DIM;
        const float* sv_ = sbuf + 2 * SEQ * DIM;
        const float scale = 0.35355339059327373f;  // 1/sqrt(8)

        const float* q1p = sbuf + p  * DIM + h * 8;
        const float* q2p = sbuf + i2 * DIM + h * 8;
        float4 q1a = *(const float4*)q1p, q1b = *(const float4*)(q1p + 4);
        float4 q2a = *(const float4*)q2p, q2b = *(const float4*)(q2p + 4);
        q1a.x *= scale; q1a.y *= scale; q1a.z *= scale; q1a.w *= scale;
        q1b.x *= scale; q1b.y *= scale; q1b.z *= scale; q1b.w *= scale;
        q2a.x *= scale; q2a.y *= scale; q2a.z *= scale; q2a.w *= scale;
        q2b.x *= scale; q2b.y *= scale; q2b.z *= scale; q2b.w *= scale;

        float ssum1 = 0.f, ssum2 = 0.f;
        float4 a1a = make_float4(0.f,0.f,0.f,0.f), a1b = make_float4(0.f,0.f,0.f,0.f);
        float4 a2a = make_float4(0.f,0.f,0.f,0.f), a2b = make_float4(0.f,0.f,0.f,0.f);

        for (int j = 0; j <= i2; j++) {
            const float* kr = sk_ + j * DIM + h * 8;
            float4 k0 = *(const float4*)kr;
            float4 k1 = *(const float4*)(kr + 4);
            const float* vr = sv_ + j * DIM + h * 8;
            float4 v0 = *(const float4*)vr;
            float4 v1 = *(const float4*)(vr + 4);

            float d2 = q2a.x*k0.x + q2a.y*k0.y + q2a.z*k0.z + q2a.w*k0.w
                     + q2b.x*k1.x + q2b.y*k1.y + q2b.z*k1.z + q2b.w*k1.w;
            float w2 = __expf(d2);
            ssum2 += w2;
            a2a.x = fmaf(w2, v0.x, a2a.x); a2a.y = fmaf(w2, v0.y, a2a.y);
            a2a.z = fmaf(w2, v0.z, a2a.z); a2a.w = fmaf(w2, v0.w, a2a.w);
            a2b.x = fmaf(w2, v1.x, a2b.x); a2b.y = fmaf(w2, v1.y, a2b.y);
            a2b.z = fmaf(w2, v1.z, a2b.z); a2b.w = fmaf(w2, v1.w, a2b.w);

            if (j <= p) {
                float d1 = q1a.x*k0.x + q1a.y*k0.y + q1a.z*k0.z + q1a.w*k0.w
                         + q1b.x*k1.x + q1b.y*k1.y + q1b.z*k1.z + q1b.w*k1.w;
                float w1 = __expf(d1);
                ssum1 += w1;
                a1a.x = fmaf(w1, v0.x, a1a.x); a1a.y = fmaf(w1, v0.y, a1a.y);
                a1a.z = fmaf(w1, v0.z, a1a.z); a1a.w = fmaf(w1, v0.w, a1a.w);
                a1b.x = fmaf(w1, v1.x, a1b.x); a1b.y = fmaf(w1, v1.y, a1b.y);
                a1b.z = fmaf(w1, v1.z, a1b.z); a1b.w = fmaf(w1, v1.w, a1b.w);
            }
        }
        float inv1 = 1.0f / ssum1;
        float inv2 = 1.0f / ssum2;
        a1a.x *= inv1; a1a.y *= inv1; a1a.z *= inv1; a1a.w *= inv1;
        a1b.x *= inv1; a1b.y *= inv1; a1b.z *= inv1; a1b.w *= inv1;
        a2a.x *= inv2; a2a.y *= inv2; a2a.z *= inv2; a2a.w *= inv2;
        a2b.x *= inv2; a2b.y *= inv2; a2b.z *= inv2; a2b.w *= inv2;

        float* c1 = sbuf + p  * DIM + h * 8;
        float* c2 = sbuf + i2 * DIM + h * 8;
        *(float4*)c1 = a1a; *(float4*)(c1 + 4) = a1b;
        *(float4*)c2 = a2a; *(float4*)(c2 + 4) = a2b;
    }
    __syncthreads();

    // ---- output projection + residual, k-split (Wo register-resident) ----
    {
        float wreg0[16], wreg1[16];
        const float* w0 = sW + (3 * DIM + cc) * WP + kh * 16;
        const float* w1 = sW + (3 * DIM + cc + 16) * WP + kh * 16;
        #pragma unroll
        for (int d = 0; d < 16; d++) { wreg0[d] = w0[d]; wreg1[d] = w1[d]; }
        const float b2 = sboS[lane];
        float* ob = out + boff;
        const int r0 = (wid * SEQ) >> 3;
        const int r1 = ((wid + 1) * SEQ) >> 3;
        for (int r = r0; r < r1; r++) {
            const float4* xr = (const float4*)(sbuf + r * DIM + kh * 16);
            float p0a = 0.f, p0b = 0.f, p1a = 0.f, p1b = 0.f;
            #pragma unroll
            for (int i = 0; i < 4; i++) {
                float4 xv = xr[i];
                p0a = fmaf(xv.x, wreg0[4*i+0], fmaf(xv.y, wreg0[4*i+1], p0a));
                p0b = fmaf(xv.z, wreg0[4*i+2], fmaf(xv.w, wreg0[4*i+3], p0b));
                p1a = fmaf(xv.x, wreg1[4*i+0], fmaf(xv.y, wreg1[4*i+1], p1a));
                p1b = fmaf(xv.z, wreg1[4*i+2], fmaf(xv.w, wreg1[4*i+3], p1b));
            }
            float part0 = p0a + p0b;
            float part1 = p1a + p1b;
            part0 += __shfl_xor_sync(FULLM, part0, 16);
            part1 += __shfl_xor_sync(FULLM, part1, 16);
            float dot = (kh ? part1 : part0) + b2;
            ob[r * DIM + lane] = dot + Qb[r * DIM + lane];
        }
    }
}

extern "C" void kernel_launch(void* const* d_in, const int* in_sizes, int n_in,
                              void* d_out, int out_size) {
    const float* Q    = (const float*)d_in[0];
    const float* K    = (const float*)d_in[1];
    const float* V    = (const float*)d_in[2];
    // d_in[3] = mask (static causal triu, implemented analytically)
    const float* ln_g = (const float*)d_in[4];
    const float* ln_b = (const float*)d_in[5];
    const float* Wq   = (const float*)d_in[6];
    const float* bq   = (const float*)d_in[7];
    const float* Wk   = (const float*)d_in[8];
    const float* bk   = (const float*)d_in[9];
    const float* Wv   = (const float*)d_in[10];
    const float* bv   = (const float*)d_in[11];
    const float* Wo   = (const float*)d_in[12];
    const float* bo   = (const float*)d_in[13];
    float* out = (float*)d_out;

    const int B = in_sizes[0] / (SEQ * DIM);  // 16384
    prep_kernel<<<1, 96>>>(ln_g, ln_b, Wq, bq, Wk, bk, Wv, bv);
    mha_fused_kernel<<<B, NTHR>>>(Q, K, V, Wo, bo, out);
}

// round 8
// speedup vs baseline: 1.4150x; 1.0444x over previous
#include <cuda_runtime.h>
#include <math.h>

#define SEQ 50
#define DIM 32
#define NTHR 256
#define NWARP 8
#define FULLM 0xffffffffu
#define WPITCH 33

// Folded weights, shared by all batches (computed once by prep_kernel)
__device__ float gWfold[3 * DIM * DIM];   // rows pre-scaled by ln_g
__device__ float gB2[3 * DIM];            // bias + b . W^T
__device__ float gSw[3 * DIM];            // rowsum of g-scaled W

__global__ void prep_kernel(
    const float* __restrict__ ln_g, const float* __restrict__ ln_b,
    const float* __restrict__ Wq, const float* __restrict__ bq,
    const float* __restrict__ Wk, const float* __restrict__ bk,
    const float* __restrict__ Wv, const float* __restrict__ bv)
{
    int j = threadIdx.x;
    if (j >= 3 * DIM) return;
    int t = j >> 5, r = j & 31;
    const float* W    = (t == 0) ? Wq : (t == 1) ? Wk : Wv;
    const float* bias = (t == 0) ? bq : (t == 1) ? bk : bv;
    float b2 = bias[r], sw = 0.f;
    #pragma unroll
    for (int d = 0; d < DIM; d++) {
        float w  = W[r * DIM + d];
        float gw = w * ln_g[d];
        b2 = fmaf(w, ln_b[d], b2);
        sw += gw;
        gWfold[(t * DIM + r) * DIM + d] = gw;
    }
    gB2[j] = b2;
    gSw[j] = sw;
}

__global__ __launch_bounds__(NTHR, 4) void mha_fused_kernel(
    const float* __restrict__ Q, const float* __restrict__ K, const float* __restrict__ V,
    const float* __restrict__ Wo, const float* __restrict__ bo,
    float* __restrict__ out)
{
    __shared__ __align__(16) float sbuf[3 * SEQ * DIM];  // raw rows -> projected in place; q -> ctx
    __shared__ float sW[4 * DIM * WPITCH];               // folded Wq,Wk,Wv + raw Wo, pitch 33
    __shared__ float2 sStats[3 * SEQ];                   // (mu, inv) per row
    __shared__ float sB2[3 * DIM], sSw[3 * DIM], sbo[DIM];

    const int tid  = threadIdx.x;
    const int lane = tid & 31;
    const int wid  = tid >> 5;
    const size_t boff = (size_t)blockIdx.x * (SEQ * DIM);
    const float* Qb = Q + boff;
    const float* Kb = K + boff;
    const float* Vb = V + boff;

    // ---- stage weights (folded qkv from global, Wo raw) into padded smem ----
    for (int i = tid; i < 4 * DIM * DIM; i += NTHR) {
        int t = i >> 10, idx = i & 1023;
        int r = idx >> 5, c = idx & 31;
        float v = (t < 3) ? gWfold[i] : Wo[idx];
        sW[t * DIM * WPITCH + r * WPITCH + c] = v;
    }
    if (tid < 3 * DIM) { sB2[tid] = gB2[tid]; sSw[tid] = gSw[tid]; }
    if (tid < DIM) sbo[tid] = bo[tid];

    // ---- raw row loads + LN stats (sum x, sum x^2), 4 rows per warp-iter ----
    {
        const int rsub = lane >> 3;
        const int rk   = lane & 7;
        for (int blk = wid; blk < (3 * SEQ + 3) / 4; blk += NWARP) {
            int gr = blk * 4 + rsub;
            float4 xv = make_float4(0.f, 0.f, 0.f, 0.f);
            if (gr < 3 * SEQ) {
                int t = gr / SEQ;
                int r = gr - t * SEQ;
                const float* src = (t == 0) ? Qb : (t == 1) ? Kb : Vb;
                xv = *(const float4*)(src + r * DIM + rk * 4);
                *(float4*)(sbuf + gr * DIM + rk * 4) = xv;
            }
            float s1 = xv.x + xv.y + xv.z + xv.w;
            float s2 = xv.x * xv.x + xv.y * xv.y + xv.z * xv.z + xv.w * xv.w;
            #pragma unroll
            for (int o = 4; o; o >>= 1) {
                s1 += __shfl_xor_sync(FULLM, s1, o);
                s2 += __shfl_xor_sync(FULLM, s2, o);
            }
            if (rk == 0 && gr < 3 * SEQ) {
                float mu  = s1 * (1.0f / DIM);
                float var = s2 * (1.0f / DIM) - mu * mu;
                sStats[gr] = make_float2(mu, rsqrtf(var + 1e-5f));
            }
        }
    }
    __syncthreads();

    // ---- projections (R4 shape): warp w handles tasks 3w..3w+2; wreg reloaded on t change
    {
        float wreg[DIM];
        float b2 = 0.f, swv = 0.f;
        int tprev = -1;
        #pragma unroll
        for (int k = 0; k < 3; k++) {
            const int task = wid * 3 + k;
            const int t = task >> 3;
            const int c = task & 7;
            if (t != tprev) {
                const float* wr = sW + (t * DIM + lane) * WPITCH;
                #pragma unroll
                for (int d = 0; d < DIM; d++) wreg[d] = wr[d];
                b2  = sB2[t * DIM + lane];
                swv = sSw[t * DIM + lane];
                tprev = t;
            }
            const int r0 = (c * SEQ) >> 3;
            const int r1 = ((c + 1) * SEQ) >> 3;
            float* base = sbuf + t * SEQ * DIM;
            float orow[7];
            const int nr = r1 - r0;
            #pragma unroll
            for (int r = 0; r < 7; r++) {
                if (r < nr) {
                    const float4* xr = (const float4*)(base + (r0 + r) * DIM);
                    float dot = 0.f;
                    #pragma unroll
                    for (int k2 = 0; k2 < 8; k2++) {
                        float4 xv = xr[k2];
                        dot = fmaf(xv.x, wreg[k2 * 4 + 0],
                              fmaf(xv.y, wreg[k2 * 4 + 1],
                              fmaf(xv.z, wreg[k2 * 4 + 2],
                              fmaf(xv.w, wreg[k2 * 4 + 3], dot))));
                    }
                    float2 st = sStats[t * SEQ + r0 + r];
                    orow[r] = fmaf(st.y, fmaf(-st.x, swv, dot), b2);
                }
            }
            __syncwarp();
            #pragma unroll
            for (int r = 0; r < 7; r++)
                if (r < nr) base[(r0 + r) * DIM + lane] = orow[r];
        }
    }
    __syncthreads();

    // ---- attention, j-split half-warp pairing:
    // warp w, lane L: sub=L&15, half=L>>4; qp = w*4 + (sub>>2), h = sub&3.
    // Queries i1=qp, i2=49-qp. half0 sweeps j in [0,jm), half1 [jm, i2];
    // partial softmax sums/accumulators combined via shfl_xor(16).
    if (tid < 224) {
        const int sub  = lane & 15;
        const int half = lane >> 4;
        int qp = wid * 4 + (sub >> 2);
        const bool valid = (qp < 25);
        if (!valid) qp = 24;               // clamp for safe indexing; no writes
        const int h  = sub & 3;
        const int i1 = qp;
        const int i2 = SEQ - 1 - qp;
        const int jm = (i2 + 1) >> 1;
        const int jbeg = half ? jm : 0;
        const int jend = half ? (i2 + 1) : jm;

        const float* sk_ = sbuf + SEQ * DIM;
        const float* sv_ = sbuf + 2 * SEQ * DIM;
        const float scale = 0.35355339059327373f;  // 1/sqrt(8)

        const float* q1p = sbuf + i1 * DIM + h * 8;
        const float* q2p = sbuf + i2 * DIM + h * 8;
        float4 q1a = *(const float4*)q1p, q1b = *(const float4*)(q1p + 4);
        float4 q2a = *(const float4*)q2p, q2b = *(const float4*)(q2p + 4);
        q1a.x *= scale; q1a.y *= scale; q1a.z *= scale; q1a.w *= scale;
        q1b.x *= scale; q1b.y *= scale; q1b.z *= scale; q1b.w *= scale;
        q2a.x *= scale; q2a.y *= scale; q2a.z *= scale; q2a.w *= scale;
        q2b.x *= scale; q2b.y *= scale; q2b.z *= scale; q2b.w *= scale;

        float ssum1 = 0.f, ssum2 = 0.f;
        float4 a1a = make_float4(0.f,0.f,0.f,0.f), a1b = make_float4(0.f,0.f,0.f,0.f);
        float4 a2a = make_float4(0.f,0.f,0.f,0.f), a2b = make_float4(0.f,0.f,0.f,0.f);

        for (int j = jbeg; j < jend; j++) {
            const float* kr = sk_ + j * DIM + h * 8;
            float4 k0 = *(const float4*)kr;
            float4 k1 = *(const float4*)(kr + 4);
            const float* vr = sv_ + j * DIM + h * 8;
            float4 v0 = *(const float4*)vr;
            float4 v1 = *(const float4*)(vr + 4);

            float d2 = q2a.x*k0.x + q2a.y*k0.y + q2a.z*k0.z + q2a.w*k0.w
                     + q2b.x*k1.x + q2b.y*k1.y + q2b.z*k1.z + q2b.w*k1.w;
            float w2 = __expf(d2);
            ssum2 += w2;
            a2a.x = fmaf(w2, v0.x, a2a.x); a2a.y = fmaf(w2, v0.y, a2a.y);
            a2a.z = fmaf(w2, v0.z, a2a.z); a2a.w = fmaf(w2, v0.w, a2a.w);
            a2b.x = fmaf(w2, v1.x, a2b.x); a2b.y = fmaf(w2, v1.y, a2b.y);
            a2b.z = fmaf(w2, v1.z, a2b.z); a2b.w = fmaf(w2, v1.w, a2b.w);

            if (j <= i1) {
                float d1 = q1a.x*k0.x + q1a.y*k0.y + q1a.z*k0.z + q1a.w*k0.w
                         + q1b.x*k1.x + q1b.y*k1.y + q1b.z*k1.z + q1b.w*k1.w;
                float w1 = __expf(d1);
                ssum1 += w1;
                a1a.x = fmaf(w1, v0.x, a1a.x); a1a.y = fmaf(w1, v0.y, a1a.y);
                a1a.z = fmaf(w1, v0.z, a1a.z); a1a.w = fmaf(w1, v0.w, a1a.w);
                a1b.x = fmaf(w1, v1.x, a1b.x); a1b.y = fmaf(w1, v1.y, a1b.y);
                a1b.z = fmaf(w1, v1.z, a1b.z); a1b.w = fmaf(w1, v1.w, a1b.w);
            }
        }

        // combine halves (lane L <-> L+16)
        ssum1 += __shfl_xor_sync(FULLM, ssum1, 16);
        ssum2 += __shfl_xor_sync(FULLM, ssum2, 16);
        a1a.x += __shfl_xor_sync(FULLM, a1a.x, 16);
        a1a.y += __shfl_xor_sync(FULLM, a1a.y, 16);
        a1a.z += __shfl_xor_sync(FULLM, a1a.z, 16);
        a1a.w += __shfl_xor_sync(FULLM, a1a.w, 16);
        a1b.x += __shfl_xor_sync(FULLM, a1b.x, 16);
        a1b.y += __shfl_xor_sync(FULLM, a1b.y, 16);
        a1b.z += __shfl_xor_sync(FULLM, a1b.z, 16);
        a1b.w += __shfl_xor_sync(FULLM, a1b.w, 16);
        a2a.x += __shfl_xor_sync(FULLM, a2a.x, 16);
        a2a.y += __shfl_xor_sync(FULLM, a2a.y, 16);
        a2a.z += __shfl_xor_sync(FULLM, a2a.z, 16);
        a2a.w += __shfl_xor_sync(FULLM, a2a.w, 16);
        a2b.x += __shfl_xor_sync(FULLM, a2b.x, 16);
        a2b.y += __shfl_xor_sync(FULLM, a2b.y, 16);
        a2b.z += __shfl_xor_sync(FULLM, a2b.z, 16);
        a2b.w += __shfl_xor_sync(FULLM, a2b.w, 16);

        if (valid && half == 0) {
            float inv1 = 1.0f / ssum1;
            float inv2 = 1.0f / ssum2;
            a1a.x *= inv1; a1a.y *= inv1; a1a.z *= inv1; a1a.w *= inv1;
            a1b.x *= inv1; a1b.y *= inv1; a1b.z *= inv1; a1b.w *= inv1;
            a2a.x *= inv2; a2a.y *= inv2; a2a.z *= inv2; a2a.w *= inv2;
            a2b.x *= inv2; a2b.y *= inv2; a2b.z *= inv2; a2b.w *= inv2;
            float* c1 = sbuf + i1 * DIM + h * 8;
            float* c2 = sbuf + i2 * DIM + h * 8;
            *(float4*)c1 = a1a; *(float4*)(c1 + 4) = a1b;
            *(float4*)c2 = a2a; *(float4*)(c2 + 4) = a2b;
        }
    }
    __syncthreads();

    // ---- output projection + residual (Wo register-resident) ----
    {
        const float* wr = sW + (3 * DIM + lane) * WPITCH;
        float wreg[DIM];
        #pragma unroll
        for (int d = 0; d < DIM; d++) wreg[d] = wr[d];
        const float b2 = sbo[lane];
        float* ob = out + boff;
        const int r0 = (wid * SEQ) >> 3;
        const int r1 = ((wid + 1) * SEQ) >> 3;
        for (int r = r0; r < r1; r++) {
            const float4* xr = (const float4*)(sbuf + r * DIM);
            float dot = b2;
            #pragma unroll
            for (int k2 = 0; k2 < 8; k2++) {
                float4 xv = xr[k2];
                dot = fmaf(xv.x, wreg[k2 * 4 + 0],
                      fmaf(xv.y, wreg[k2 * 4 + 1],
                      fmaf(xv.z, wreg[k2 * 4 + 2],
                      fmaf(xv.w, wreg[k2 * 4 + 3], dot))));
            }
            ob[r * DIM + lane] = dot + Qb[r * DIM + lane];
        }
    }
}

extern "C" void kernel_launch(void* const* d_in, const int* in_sizes, int n_in,
                              void* d_out, int out_size) {
    const float* Q    = (const float*)d_in[0];
    const float* K    = (const float*)d_in[1];
    const float* V    = (const float*)d_in[2];
    // d_in[3] = mask (static causal triu, implemented analytically)
    const float* ln_g = (const float*)d_in[4];
    const float* ln_b = (const float*)d_in[5];
    const float* Wq   = (const float*)d_in[6];
    const float* bq   = (const float*)d_in[7];
    const float* Wk   = (const float*)d_in[8];
    const float* bk   = (const float*)d_in[9];
    const float* Wv   = (const float*)d_in[10];
    const float* bv   = (const float*)d_in[11];
    const float* Wo   = (const float*)d_in[12];
    const float* bo   = (const float*)d_in[13];
    float* out = (float*)d_out;

    const int B = in_sizes[0] / (SEQ * DIM);  // 16384
    prep_kernel<<<1, 96>>>(ln_g, ln_b, Wq, bq, Wk, bk, Wv, bv);
    mha_fused_kernel<<<B, NTHR>>>(Q, K, V, Wo, bo, out);
}